// round 16
// baseline (speedup 1.0000x reference)
#include <cuda_runtime.h>
#include <cuda_fp16.h>
#include <cstdint>
#include <math.h>

typedef __half fp16;

// Problem constants
#define BATCH   4
#define SEQ     2048
#define DM      2048
#define NH      16
#define DH      128
#define MROWS   (BATCH * SEQ)   // 8192
#define QKV_N   (3 * DM)        // 6144

// ---------------------------------------------------------------------------
// Device scratch (allocation-free per harness rules)
// ---------------------------------------------------------------------------
__device__ fp16 g_xh [(size_t)MROWS * DM];          // x fp16
__device__ fp16 g_qkvhi[(size_t)MROWS * QKV_N];     // qkv (fp16, Q pre-scaled)
__device__ fp16 g_ahi[(size_t)MROWS * DM];          // attn out (fp16)
__device__ fp16 g_wqt[(size_t)QKV_N * DM];          // w_qkv^T [N,K] fp16
__device__ fp16 g_wot[(size_t)DM * DM];             // w_out^T [N,K] fp16

// ---------------------------------------------------------------------------
// Helpers
// ---------------------------------------------------------------------------
__device__ __forceinline__ uint32_t smem_u32(const void* p) {
    uint32_t a;
    asm("{ .reg .u64 t; cvta.to.shared.u64 t, %1; cvt.u32.u64 %0, t; }"
        : "=r"(a) : "l"(p));
    return a;
}

__device__ __forceinline__ uint32_t pack_f16(float a, float b) {
    __half2 t = __floats2half2_rn(a, b);
    return *reinterpret_cast<uint32_t*>(&t);
}

__device__ __forceinline__ void cp16(uint32_t dst, const void* src) {
    asm volatile("cp.async.cg.shared.global [%0], [%1], 16;\n"
                 :: "r"(dst), "l"(src));
}
#define CP_COMMIT() asm volatile("cp.async.commit_group;\n")
#define CP_WAIT(N)  asm volatile("cp.async.wait_group %0;\n" :: "n"(N))

__device__ __forceinline__ void ldmatrix_x4(uint32_t& r0, uint32_t& r1,
                                            uint32_t& r2, uint32_t& r3,
                                            uint32_t addr) {
    asm volatile("ldmatrix.sync.aligned.m8n8.x4.shared.b16 {%0,%1,%2,%3}, [%4];\n"
                 : "=r"(r0), "=r"(r1), "=r"(r2), "=r"(r3) : "r"(addr));
}
__device__ __forceinline__ void ldmatrix_x4_trans(uint32_t& r0, uint32_t& r1,
                                                  uint32_t& r2, uint32_t& r3,
                                                  uint32_t addr) {
    asm volatile("ldmatrix.sync.aligned.m8n8.x4.trans.shared.b16 {%0,%1,%2,%3}, [%4];\n"
                 : "=r"(r0), "=r"(r1), "=r"(r2), "=r"(r3) : "r"(addr));
}

__device__ __forceinline__ void mma_f16(float* d, const uint32_t* a, const uint32_t* b)
{
    asm volatile(
        "mma.sync.aligned.m16n8k16.row.col.f32.f16.f16.f32 "
        "{%0,%1,%2,%3}, {%4,%5,%6,%7}, {%8,%9}, {%0,%1,%2,%3};\n"
        : "+f"(d[0]), "+f"(d[1]), "+f"(d[2]), "+f"(d[3])
        : "r"(a[0]), "r"(a[1]), "r"(a[2]), "r"(a[3]),
          "r"(b[0]), "r"(b[1]));
}

// ---------------------------------------------------------------------------
// Elementwise fp32 -> fp16 convert
// ---------------------------------------------------------------------------
__global__ void cvt_f16_kernel(const float4* __restrict__ src,
                               __half2* __restrict__ dst, int n4)
{
    int idx = blockIdx.x * blockDim.x + threadIdx.x;
    if (idx >= n4) return;
    float4 v = src[idx];
    dst[idx * 2 + 0] = __floats2half2_rn(v.x, v.y);
    dst[idx * 2 + 1] = __floats2half2_rn(v.z, v.w);
}

// ---------------------------------------------------------------------------
// Transpose + fp16 round: src [K,N] fp32 -> hi [N,K] fp16
// ---------------------------------------------------------------------------
__global__ void transpose_f16_kernel(const float* __restrict__ src,
                                     fp16* __restrict__ hi,
                                     int K, int N)
{
    __shared__ float t[32][33];
    int nb = blockIdx.x * 32, kb = blockIdx.y * 32;
    int tx = threadIdx.x, ty = threadIdx.y;
#pragma unroll
    for (int i = 0; i < 4; i++)
        t[ty + i * 8][tx] = src[(size_t)(kb + ty + i * 8) * N + nb + tx];
    __syncthreads();
#pragma unroll
    for (int i = 0; i < 4; i++) {
        float v = t[tx][ty + i * 8];
        hi[(size_t)(nb + ty + i * 8) * K + kb + tx] = __float2half_rn(v);
    }
}

// ---------------------------------------------------------------------------
// Pure-fp16 tensor-core GEMM, persistent-CTA tile loop.
// 128 threads (4 warps), warp tile 64x64, BK=64, 2-stage cp.async.
// Next tile's stage-0 prefetch replaces the final k-iteration prefetch, so
// the inter-tile pipeline bubble hides under the epilogue.
// Scale fold: F16_OUT multiplies (acc+bias) by qscale for cols < qlim.
// ---------------------------------------------------------------------------
#define LDT 72
#define G_TILE (128 * LDT)               // 9216 elems per operand tile
#define G_STAGE_E (2 * G_TILE)           // A | B
#define GEMM_SMEM_BYTES (2 * G_STAGE_E * 2)   // 73728

template<bool F16_OUT>
__global__ __launch_bounds__(128, 2) void gemm_tc_kernel(
    const fp16* __restrict__ Ah,
    const fp16* __restrict__ Bh,
    const float* __restrict__ bias,
    float* __restrict__ Cf, fp16* __restrict__ Chi,
    int M, int N, int K, float qscale, int qlim)
{
    extern __shared__ fp16 gsm[];
    const uint32_t sb = smem_u32(gsm);

    const int tid  = threadIdx.x;
    const int lane = tid & 31;
    const int warp = tid >> 5;            // 0..3
    const int wm = (warp >> 1) * 64;      // 0,64
    const int wn = (warp & 1) * 64;       // 0,64
    const int g   = lane >> 2;
    const int tig = lane & 3;

    const int a_r = lane & 15;
    const int a_c = (lane >> 4) * 8;
    const int b_r = ((lane >> 4) * 8) + (lane & 7);
    const int b_c = ((lane >> 3) & 1) * 8;

    const int nx = N >> 7;
    const int T  = nx * (M >> 7);
    const int nk = K >> 6;   // K / 64

    int tile = blockIdx.x;
    if (tile >= T) return;

    // issue stage `buf` for k-block t of tile (bm,bn)
    auto issue = [&](int bm, int bn, int t, int buf) {
        int k0 = t << 6;
        uint32_t stb = sb + (uint32_t)(buf * G_STAGE_E) * 2;
        const fp16* s0 = Ah + (size_t)bm * K;
        const fp16* s1 = Bh + (size_t)bn * K;
#pragma unroll
        for (int jj = 0; jj < 16; jj++) {
            const int tl = jj >> 3;
            int q  = tid + (jj & 7) * 128;
            int r  = q >> 3;
            int ch = (q & 7) << 3;
            const fp16* src = (tl == 0 ? s0 : s1) + (size_t)r * K + k0 + ch;
            cp16(stb + (uint32_t)(tl * G_TILE + r * LDT + ch) * 2, src);
        }
        CP_COMMIT();
    };

    int bm = (tile / nx) << 7;
    int bn = (tile % nx) << 7;
    int gt = 0;                    // global buffer counter (parity = buffer)
    issue(bm, bn, 0, 0);

    while (true) {
        const int ntile = tile + gridDim.x;
        const int nbm = (ntile / nx) << 7;
        const int nbn = (ntile % nx) << 7;

        float acc[4][8][4];
#pragma unroll
        for (int mt = 0; mt < 4; mt++)
#pragma unroll
            for (int nt = 0; nt < 8; nt++)
#pragma unroll
                for (int i = 0; i < 4; i++) acc[mt][nt][i] = 0.0f;

        for (int t = 0; t < nk; t++) {
            // prefetch: next k-block, or next tile's stage 0
            if (t + 1 < nk)       issue(bm, bn, t + 1, (gt + 1) & 1);
            else if (ntile < T)   issue(nbm, nbn, 0,   (gt + 1) & 1);
            else                  CP_COMMIT();
            CP_WAIT(1);
            __syncthreads();
            const uint32_t cb = sb + (uint32_t)((gt & 1) * G_STAGE_E) * 2;

#pragma unroll
            for (int ks = 0; ks < 64; ks += 16) {
                uint32_t ah[4][4], bh[4][4];
#pragma unroll
                for (int mt = 0; mt < 4; mt++) {
                    uint32_t ao = cb + (uint32_t)((wm + mt * 16 + a_r) * LDT
                                                  + ks + a_c) * 2;
                    ldmatrix_x4(ah[mt][0], ah[mt][1], ah[mt][2], ah[mt][3], ao);
                }
#pragma unroll
                for (int ntp = 0; ntp < 4; ntp++) {
                    uint32_t bo = cb + (uint32_t)(G_TILE +
                                   (wn + ntp * 16 + b_r) * LDT + ks + b_c) * 2;
                    ldmatrix_x4(bh[ntp][0], bh[ntp][1], bh[ntp][2], bh[ntp][3], bo);
                }
#pragma unroll
                for (int mt = 0; mt < 4; mt++)
#pragma unroll
                    for (int ntp = 0; ntp < 4; ntp++) {
                        mma_f16(acc[mt][2 * ntp],     ah[mt], bh[ntp]);
                        mma_f16(acc[mt][2 * ntp + 1], ah[mt], bh[ntp] + 2);
                    }
            }
            __syncthreads();
            gt++;
        }

        // epilogue (next tile's stage 0 loads in background)
#pragma unroll
        for (int nt = 0; nt < 8; nt++) {
            int col = bn + wn + nt * 8 + tig * 2;
            float b0 = bias[col];
            float b1 = bias[col + 1];
            float sc = (F16_OUT && col < qlim) ? qscale : 1.0f;
#pragma unroll
            for (int mt = 0; mt < 4; mt++) {
                int row = bm + wm + mt * 16 + g;
                float v00 = (acc[mt][nt][0] + b0) * sc;
                float v01 = (acc[mt][nt][1] + b1) * sc;
                float v10 = (acc[mt][nt][2] + b0) * sc;
                float v11 = (acc[mt][nt][3] + b1) * sc;
                if (F16_OUT) {
                    size_t i0 = (size_t)row * N + col;
                    size_t i1 = (size_t)(row + 8) * N + col;
                    *reinterpret_cast<uint32_t*>(&Chi[i0]) = pack_f16(v00, v01);
                    *reinterpret_cast<uint32_t*>(&Chi[i1]) = pack_f16(v10, v11);
                } else {
                    float2 w0 = {v00, v01}, w1 = {v10, v11};
                    *reinterpret_cast<float2*>(&Cf[(size_t)row * N + col])       = w0;
                    *reinterpret_cast<float2*>(&Cf[(size_t)(row + 8) * N + col]) = w1;
                }
            }
        }

        if (ntile >= T) break;
        tile = ntile; bm = nbm; bn = nbn;
    }
}

// ---------------------------------------------------------------------------
// Tensor-core flash attention, pure fp16, 128 threads (4 warps x 32 Q rows).
// Q pre-scaled by 1/sqrt(dh) in GEMM1 epilogue (no scale multiply here).
// V fragments shared across both row bands. KTILE=64 double-buffered,
// single barrier per iter, 2 CTAs/SM.
// ---------------------------------------------------------------------------
#define LDQ 136
#define QTILE 128
#define KTILE 64
#define A_SM_KV (QTILE * LDQ)
#define A_KV_TILE (KTILE * LDQ)               // 8704 elems
#define A_KV_STAGE (2 * A_KV_TILE)            // K | V
#define ATTN_SMEM_ELEMS (A_SM_KV + 2 * A_KV_STAGE)
#define ATTN_SMEM_BYTES (ATTN_SMEM_ELEMS * 2) // 104448

__global__ __launch_bounds__(128, 2) void attn_tc_kernel(
    const fp16* __restrict__ qkvhi, fp16* __restrict__ ahi)
{
    extern __shared__ fp16 asmem[];
    const uint32_t sb = smem_u32(asmem);

    const int qt = (int)gridDim.x - 1 - (int)blockIdx.x;   // heavy tiles first
    const int h  = blockIdx.y;
    const int b  = blockIdx.z;

    const int tid  = threadIdx.x;
    const int lane = tid & 31;
    const int warp = tid >> 5;          // 0..3
    const int g    = lane >> 2;
    const int tig  = lane & 3;
    const int wr   = warp * 32;         // warp's 32-row band

    const int a_r  = lane & 15;
    const int a_c  = (lane >> 4) * 8;
    const int kb_r = ((lane >> 4) * 8) + (lane & 7);
    const int kb_c = ((lane >> 3) & 1) * 8;
    const int vb_r = (lane & 7) + ((lane >> 3) & 1) * 8;
    const int vb_c = (lane >> 4) * 8;

    const size_t qoff = (size_t)(b * SEQ) * QKV_N + h * DH;
    const size_t koff = qoff + DM;
    const size_t voff = qoff + 2 * DM;

    const int njt = 2 * qt + 2;

    auto issue_kv = [&](int j) {
        if (j < njt) {
            uint32_t stb = sb + (uint32_t)(A_SM_KV + (j & 1) * A_KV_STAGE) * 2;
#pragma unroll
            for (int jj = 0; jj < 16; jj++) {
                const int tile = jj >> 3;
                int q  = tid + (jj & 7) * 128;
                int r  = q >> 4;
                int ch = (q & 15) << 3;
                size_t grow = (size_t)(j * KTILE + r) * QKV_N + ch;
                const fp16* src = qkvhi + (tile == 0 ? koff : voff) + grow;
                cp16(stb + (uint32_t)(tile * A_KV_TILE + r * LDQ + ch) * 2, src);
            }
        }
        CP_COMMIT();
    };

    {
#pragma unroll
        for (int jj = 0; jj < 16; jj++) {
            int q  = tid + jj * 128;
            int r  = q >> 4;
            int ch = (q & 15) << 3;
            const fp16* src = qkvhi + qoff
                              + (size_t)(qt * QTILE + r) * QKV_N + ch;
            cp16(sb + (uint32_t)(r * LDQ + ch) * 2, src);
        }
        issue_kv(0);   // Q + KV(0) in one group
    }

    float m[2][2], l[2][2];
#pragma unroll
    for (int mt = 0; mt < 2; mt++) {
        m[mt][0] = -INFINITY; m[mt][1] = -INFINITY;
        l[mt][0] = 0.0f;      l[mt][1] = 0.0f;
    }
    float o[2][16][4];
#pragma unroll
    for (int mt = 0; mt < 2; mt++)
#pragma unroll
        for (int nt = 0; nt < 16; nt++)
#pragma unroll
            for (int i = 0; i < 4; i++) o[mt][nt][i] = 0.0f;

    const int rowbase = qt * QTILE + wr;

    for (int j = 0; j < njt; j++) {
        CP_WAIT(0);
        __syncthreads();
        issue_kv(j + 1);

        if (j * KTILE <= rowbase + 31) {
            const uint32_t kvb = sb + (uint32_t)(A_SM_KV + (j & 1) * A_KV_STAGE) * 2;
            const uint32_t khi_b = kvb + (uint32_t)(kb_r * LDQ + kb_c) * 2;
            const uint32_t vhi_b = kvb + (uint32_t)(A_KV_TILE + vb_r * LDQ + vb_c) * 2;

            // ---- S = Q @ K^T (both 16-row bands; Q pre-scaled) ----
            float s[2][8][4];
#pragma unroll
            for (int mt = 0; mt < 2; mt++)
#pragma unroll
                for (int nt = 0; nt < 8; nt++)
#pragma unroll
                    for (int i = 0; i < 4; i++) s[mt][nt][i] = 0.0f;

#pragma unroll
            for (int ks = 0; ks < 8; ks++) {
                uint32_t ah[2][4];
#pragma unroll
                for (int mt = 0; mt < 2; mt++) {
                    uint32_t ao = sb + (uint32_t)((wr + mt * 16 + a_r) * LDQ
                                                  + ks * 16 + a_c) * 2;
                    ldmatrix_x4(ah[mt][0], ah[mt][1], ah[mt][2], ah[mt][3], ao);
                }
#pragma unroll
                for (int ntp = 0; ntp < 4; ntp++) {
                    uint32_t bh[4];
                    ldmatrix_x4(bh[0], bh[1], bh[2], bh[3],
                                khi_b + (uint32_t)(ntp * 16 * LDQ + ks * 16) * 2);
#pragma unroll
                    for (int mt = 0; mt < 2; mt++) {
                        mma_f16(s[mt][2 * ntp],     ah[mt], bh);
                        mma_f16(s[mt][2 * ntp + 1], ah[mt], bh + 2);
                    }
                }
            }

            const int jc = j * KTILE;
#pragma unroll
            for (int mt = 0; mt < 2; mt++) {
                const int rowg  = rowbase + mt * 16 + g;
                const int rowg8 = rowg + 8;

                if (jc + KTILE - 1 > rowg) {
#pragma unroll
                    for (int nt = 0; nt < 8; nt++) {
                        int c0 = jc + nt * 8 + tig * 2;
                        if (c0     > rowg) s[mt][nt][0] = -1e30f;
                        if (c0 + 1 > rowg) s[mt][nt][1] = -1e30f;
                    }
                }
                if (jc + KTILE - 1 > rowg8) {
#pragma unroll
                    for (int nt = 0; nt < 8; nt++) {
                        int c0 = jc + nt * 8 + tig * 2;
                        if (c0     > rowg8) s[mt][nt][2] = -1e30f;
                        if (c0 + 1 > rowg8) s[mt][nt][3] = -1e30f;
                    }
                }

                float mt0 = -1e30f, mt1 = -1e30f;
#pragma unroll
                for (int nt = 0; nt < 8; nt++) {
                    mt0 = fmaxf(mt0, fmaxf(s[mt][nt][0], s[mt][nt][1]));
                    mt1 = fmaxf(mt1, fmaxf(s[mt][nt][2], s[mt][nt][3]));
                }
                mt0 = fmaxf(mt0, __shfl_xor_sync(0xffffffffu, mt0, 1));
                mt0 = fmaxf(mt0, __shfl_xor_sync(0xffffffffu, mt0, 2));
                mt1 = fmaxf(mt1, __shfl_xor_sync(0xffffffffu, mt1, 1));
                mt1 = fmaxf(mt1, __shfl_xor_sync(0xffffffffu, mt1, 2));

                float mn0 = fmaxf(m[mt][0], mt0);
                float mn1 = fmaxf(m[mt][1], mt1);
                float al0 = __expf(m[mt][0] - mn0);
                float al1 = __expf(m[mt][1] - mn1);
                m[mt][0] = mn0; m[mt][1] = mn1;

                float rs0 = 0.0f, rs1 = 0.0f;
#pragma unroll
                for (int nt = 0; nt < 8; nt++) {
                    s[mt][nt][0] = __expf(s[mt][nt][0] - mn0); rs0 += s[mt][nt][0];
                    s[mt][nt][1] = __expf(s[mt][nt][1] - mn0); rs0 += s[mt][nt][1];
                    s[mt][nt][2] = __expf(s[mt][nt][2] - mn1); rs1 += s[mt][nt][2];
                    s[mt][nt][3] = __expf(s[mt][nt][3] - mn1); rs1 += s[mt][nt][3];
                }
                rs0 += __shfl_xor_sync(0xffffffffu, rs0, 1);
                rs0 += __shfl_xor_sync(0xffffffffu, rs0, 2);
                rs1 += __shfl_xor_sync(0xffffffffu, rs1, 1);
                rs1 += __shfl_xor_sync(0xffffffffu, rs1, 2);

                l[mt][0] = l[mt][0] * al0 + rs0;
                l[mt][1] = l[mt][1] * al1 + rs1;
#pragma unroll
                for (int nt = 0; nt < 16; nt++) {
                    o[mt][nt][0] *= al0; o[mt][nt][1] *= al0;
                    o[mt][nt][2] *= al1; o[mt][nt][3] *= al1;
                }
            }

            // ---- O += P @ V (V fragments shared across both bands) ----
#pragma unroll
            for (int ks = 0; ks < 4; ks++) {
                uint32_t ph[2][4];
#pragma unroll
                for (int mt = 0; mt < 2; mt++)
#pragma unroll
                    for (int half = 0; half < 2; half++) {
                        ph[mt][0 + 2 * half] = pack_f16(s[mt][2 * ks + half][0],
                                                        s[mt][2 * ks + half][1]);
                        ph[mt][1 + 2 * half] = pack_f16(s[mt][2 * ks + half][2],
                                                        s[mt][2 * ks + half][3]);
                    }
#pragma unroll
                for (int ntp = 0; ntp < 8; ntp++) {
                    uint32_t bh[4];
                    ldmatrix_x4_trans(bh[0], bh[1], bh[2], bh[3],
                                      vhi_b + (uint32_t)(ks * 16 * LDQ + ntp * 16) * 2);
#pragma unroll
                    for (int mt = 0; mt < 2; mt++) {
                        mma_f16(o[mt][2 * ntp],     ph[mt], bh);
                        mma_f16(o[mt][2 * ntp + 1], ph[mt], bh + 2);
                    }
                }
            }
        }
    }

    // ---- normalize + fp16 store (feeds GEMM2) ----
#pragma unroll
    for (int mt = 0; mt < 2; mt++) {
        const float inv0 = 1.0f / l[mt][0];
        const float inv1 = 1.0f / l[mt][1];
        const int rowg = rowbase + mt * 16 + g;
#pragma unroll
        for (int nt = 0; nt < 16; nt++) {
            int col = h * DH + nt * 8 + tig * 2;
            size_t i0 = (size_t)(b * SEQ + rowg)     * DM + col;
            size_t i1 = (size_t)(b * SEQ + rowg + 8) * DM + col;
            *reinterpret_cast<uint32_t*>(&ahi[i0]) =
                pack_f16(o[mt][nt][0] * inv0, o[mt][nt][1] * inv0);
            *reinterpret_cast<uint32_t*>(&ahi[i1]) =
                pack_f16(o[mt][nt][2] * inv1, o[mt][nt][3] * inv1);
        }
    }
}

// ---------------------------------------------------------------------------
extern "C" void kernel_launch(void* const* d_in, const int* in_sizes, int n_in,
                              void* d_out, int out_size)
{
    const float* x     = (const float*)d_in[0];
    const float* w_qkv = (const float*)d_in[1];
    const float* b_qkv = (const float*)d_in[2];
    const float* w_out = (const float*)d_in[3];
    const float* b_out = (const float*)d_in[4];
    float* out = (float*)d_out;

    fp16 *xh, *qh, *ahi, *wq, *wo;
    cudaGetSymbolAddress((void**)&xh,  g_xh);
    cudaGetSymbolAddress((void**)&qh,  g_qkvhi);
    cudaGetSymbolAddress((void**)&ahi, g_ahi);
    cudaGetSymbolAddress((void**)&wq,  g_wqt);
    cudaGetSymbolAddress((void**)&wo,  g_wot);

    int smCount = 148;
    cudaDeviceGetAttribute(&smCount, cudaDevAttrMultiProcessorCount, 0);
    const int pgrid = 2 * smCount;

    cudaFuncSetAttribute(attn_tc_kernel,
                         cudaFuncAttributeMaxDynamicSharedMemorySize,
                         ATTN_SMEM_BYTES);
    cudaFuncSetAttribute(gemm_tc_kernel<true>,
                         cudaFuncAttributeMaxDynamicSharedMemorySize,
                         GEMM_SMEM_BYTES);
    cudaFuncSetAttribute(gemm_tc_kernel<false>,
                         cudaFuncAttributeMaxDynamicSharedMemorySize,
                         GEMM_SMEM_BYTES);

    const float scale = 0.08838834764831845f;   // 1/sqrt(128)

    // 0a) convert x -> fp16
    {
        int n4 = (MROWS * DM) / 4;
        cvt_f16_kernel<<<n4 / 256, 256>>>((const float4*)x, (__half2*)xh, n4);
    }
    // 0b) transpose weights -> fp16
    {
        dim3 b32(32, 8);
        dim3 gq(QKV_N / 32, DM / 32);
        transpose_f16_kernel<<<gq, b32>>>(w_qkv, wq, DM, QKV_N);
        dim3 go(DM / 32, DM / 32);
        transpose_f16_kernel<<<go, b32>>>(w_out, wo, DM, DM);
    }
    // 1) QKV projection (persistent, Q cols pre-scaled by 1/sqrt(dh)) -> fp16
    {
        gemm_tc_kernel<true><<<pgrid, 128, GEMM_SMEM_BYTES>>>(
            xh, wq, b_qkv, nullptr, qh, MROWS, QKV_N, DM, scale, DM);
    }
    // 2) Attention (pure fp16, wide warp tiles, 2 CTAs/SM) -> fp16 output
    {
        dim3 g2(SEQ / QTILE, NH, BATCH);
        attn_tc_kernel<<<g2, 128, ATTN_SMEM_BYTES>>>(qh, ahi);
    }
    // 3) Output projection (persistent) -> fp32
    {
        gemm_tc_kernel<false><<<pgrid, 128, GEMM_SMEM_BYTES>>>(
            ahi, wo, b_out, out, nullptr, MROWS, DM, DM, 1.0f, 0);
    }
}

// round 17
// speedup vs baseline: 1.2050x; 1.2050x over previous
#include <cuda_runtime.h>
#include <cuda_fp16.h>
#include <cstdint>
#include <math.h>

typedef __half fp16;

// Problem constants
#define BATCH   4
#define SEQ     2048
#define DM      2048
#define NH      16
#define DH      128
#define MROWS   (BATCH * SEQ)   // 8192
#define QKV_N   (3 * DM)        // 6144

// ---------------------------------------------------------------------------
// Device scratch (allocation-free per harness rules)
// ---------------------------------------------------------------------------
__device__ fp16 g_xh [(size_t)MROWS * DM];          // x fp16
__device__ fp16 g_qkvhi[(size_t)MROWS * QKV_N];     // qkv (fp16, Q pre-scaled)
__device__ fp16 g_ahi[(size_t)MROWS * DM];          // attn out (fp16)
__device__ fp16 g_wqt[(size_t)QKV_N * DM];          // w_qkv^T [N,K] fp16
__device__ fp16 g_wot[(size_t)DM * DM];             // w_out^T [N,K] fp16

// ---------------------------------------------------------------------------
// Helpers
// ---------------------------------------------------------------------------
__device__ __forceinline__ uint32_t smem_u32(const void* p) {
    uint32_t a;
    asm("{ .reg .u64 t; cvta.to.shared.u64 t, %1; cvt.u32.u64 %0, t; }"
        : "=r"(a) : "l"(p));
    return a;
}

__device__ __forceinline__ uint32_t pack_f16(float a, float b) {
    __half2 t = __floats2half2_rn(a, b);
    return *reinterpret_cast<uint32_t*>(&t);
}

__device__ __forceinline__ void cp16(uint32_t dst, const void* src) {
    asm volatile("cp.async.cg.shared.global [%0], [%1], 16;\n"
                 :: "r"(dst), "l"(src));
}
#define CP_COMMIT() asm volatile("cp.async.commit_group;\n")
#define CP_WAIT(N)  asm volatile("cp.async.wait_group %0;\n" :: "n"(N))

__device__ __forceinline__ void ldmatrix_x4(uint32_t& r0, uint32_t& r1,
                                            uint32_t& r2, uint32_t& r3,
                                            uint32_t addr) {
    asm volatile("ldmatrix.sync.aligned.m8n8.x4.shared.b16 {%0,%1,%2,%3}, [%4];\n"
                 : "=r"(r0), "=r"(r1), "=r"(r2), "=r"(r3) : "r"(addr));
}
__device__ __forceinline__ void ldmatrix_x4_trans(uint32_t& r0, uint32_t& r1,
                                                  uint32_t& r2, uint32_t& r3,
                                                  uint32_t addr) {
    asm volatile("ldmatrix.sync.aligned.m8n8.x4.trans.shared.b16 {%0,%1,%2,%3}, [%4];\n"
                 : "=r"(r0), "=r"(r1), "=r"(r2), "=r"(r3) : "r"(addr));
}

__device__ __forceinline__ void mma_f16(float* d, const uint32_t* a, const uint32_t* b)
{
    asm volatile(
        "mma.sync.aligned.m16n8k16.row.col.f32.f16.f16.f32 "
        "{%0,%1,%2,%3}, {%4,%5,%6,%7}, {%8,%9}, {%0,%1,%2,%3};\n"
        : "+f"(d[0]), "+f"(d[1]), "+f"(d[2]), "+f"(d[3])
        : "r"(a[0]), "r"(a[1]), "r"(a[2]), "r"(a[3]),
          "r"(b[0]), "r"(b[1]));
}

// ---------------------------------------------------------------------------
// Elementwise fp32 -> fp16 convert
// ---------------------------------------------------------------------------
__global__ void cvt_f16_kernel(const float4* __restrict__ src,
                               __half2* __restrict__ dst, int n4)
{
    int idx = blockIdx.x * blockDim.x + threadIdx.x;
    if (idx >= n4) return;
    float4 v = src[idx];
    dst[idx * 2 + 0] = __floats2half2_rn(v.x, v.y);
    dst[idx * 2 + 1] = __floats2half2_rn(v.z, v.w);
}

// ---------------------------------------------------------------------------
// Transpose + fp16 round: src [K,N] fp32 -> hi [N,K] fp16
// ---------------------------------------------------------------------------
__global__ void transpose_f16_kernel(const float* __restrict__ src,
                                     fp16* __restrict__ hi,
                                     int K, int N)
{
    __shared__ float t[32][33];
    int nb = blockIdx.x * 32, kb = blockIdx.y * 32;
    int tx = threadIdx.x, ty = threadIdx.y;
#pragma unroll
    for (int i = 0; i < 4; i++)
        t[ty + i * 8][tx] = src[(size_t)(kb + ty + i * 8) * N + nb + tx];
    __syncthreads();
#pragma unroll
    for (int i = 0; i < 4; i++) {
        float v = t[tx][ty + i * 8];
        hi[(size_t)(nb + ty + i * 8) * K + kb + tx] = __float2half_rn(v);
    }
}

// ---------------------------------------------------------------------------
// Pure-fp16 tensor-core GEMM (R15 winner: static grid, 4 warps, 64x64 warp
// tile, BK=64, 2-stage cp.async). Scale fold: F16_OUT multiplies (acc+bias)
// by qscale for cols < qlim (pre-scales Q by 1/sqrt(dh) in GEMM1).
// ---------------------------------------------------------------------------
#define LDT 72
#define G_TILE (128 * LDT)               // 9216 elems per operand tile
#define G_STAGE_E (2 * G_TILE)           // A | B
#define G_STAGES 2
#define GEMM_SMEM_BYTES (G_STAGES * G_STAGE_E * 2)   // 73728

template<bool F16_OUT>
__global__ __launch_bounds__(128, 2) void gemm_tc_kernel(
    const fp16* __restrict__ Ah,
    const fp16* __restrict__ Bh,
    const float* __restrict__ bias,
    float* __restrict__ Cf, fp16* __restrict__ Chi,
    int M, int N, int K, float qscale, int qlim)
{
    extern __shared__ fp16 gsm[];
    const uint32_t sb = smem_u32(gsm);

    const int tid  = threadIdx.x;
    const int lane = tid & 31;
    const int warp = tid >> 5;            // 0..3
    const int bm = blockIdx.y * 128;
    const int bn = blockIdx.x * 128;
    const int wm = (warp >> 1) * 64;      // 0,64
    const int wn = (warp & 1) * 64;       // 0,64
    const int g   = lane >> 2;
    const int tig = lane & 3;

    const int a_r = lane & 15;
    const int a_c = (lane >> 4) * 8;
    const int b_r = ((lane >> 4) * 8) + (lane & 7);
    const int b_c = ((lane >> 3) & 1) * 8;

    const fp16* gsrc0 = Ah + (size_t)bm * K;
    const fp16* gsrc1 = Bh + (size_t)bn * K;

    const int nk = K >> 6;   // K / 64

    auto issue = [&](int t) {
        if (t < nk) {
            int k0 = t << 6;
            uint32_t stb = sb + (uint32_t)((t & (G_STAGES - 1)) * G_STAGE_E) * 2;
#pragma unroll
            for (int jj = 0; jj < 16; jj++) {
                const int tile = jj >> 3;
                int q  = tid + (jj & 7) * 128;
                int r  = q >> 3;
                int ch = (q & 7) << 3;
                const fp16* src = (tile == 0 ? gsrc0 : gsrc1)
                                  + (size_t)r * K + k0 + ch;
                cp16(stb + (uint32_t)(tile * G_TILE + r * LDT + ch) * 2, src);
            }
        }
        CP_COMMIT();
    };

    issue(0);

    float acc[4][8][4];
#pragma unroll
    for (int mt = 0; mt < 4; mt++)
#pragma unroll
        for (int nt = 0; nt < 8; nt++)
#pragma unroll
            for (int i = 0; i < 4; i++) acc[mt][nt][i] = 0.0f;

    for (int t = 0; t < nk; t++) {
        issue(t + 1);
        CP_WAIT(1);
        __syncthreads();
        const uint32_t cb = sb + (uint32_t)((t & (G_STAGES - 1)) * G_STAGE_E) * 2;

#pragma unroll
        for (int ks = 0; ks < 64; ks += 16) {
            uint32_t ah[4][4], bh[4][4];
#pragma unroll
            for (int mt = 0; mt < 4; mt++) {
                uint32_t ao = cb + (uint32_t)((wm + mt * 16 + a_r) * LDT + ks + a_c) * 2;
                ldmatrix_x4(ah[mt][0], ah[mt][1], ah[mt][2], ah[mt][3], ao);
            }
#pragma unroll
            for (int ntp = 0; ntp < 4; ntp++) {
                uint32_t bo = cb + (uint32_t)(G_TILE +
                               (wn + ntp * 16 + b_r) * LDT + ks + b_c) * 2;
                ldmatrix_x4(bh[ntp][0], bh[ntp][1], bh[ntp][2], bh[ntp][3], bo);
            }
#pragma unroll
            for (int mt = 0; mt < 4; mt++)
#pragma unroll
                for (int ntp = 0; ntp < 4; ntp++) {
                    mma_f16(acc[mt][2 * ntp],     ah[mt], bh[ntp]);
                    mma_f16(acc[mt][2 * ntp + 1], ah[mt], bh[ntp] + 2);
                }
        }
        __syncthreads();
    }

    // epilogue (scale fold for Q columns when F16_OUT)
#pragma unroll
    for (int nt = 0; nt < 8; nt++) {
        int col = bn + wn + nt * 8 + tig * 2;
        float b0 = bias[col];
        float b1 = bias[col + 1];
        float sc = (F16_OUT && col < qlim) ? qscale : 1.0f;
#pragma unroll
        for (int mt = 0; mt < 4; mt++) {
            int row = bm + wm + mt * 16 + g;
            float v00 = (acc[mt][nt][0] + b0) * sc;
            float v01 = (acc[mt][nt][1] + b1) * sc;
            float v10 = (acc[mt][nt][2] + b0) * sc;
            float v11 = (acc[mt][nt][3] + b1) * sc;
            if (F16_OUT) {
                size_t i0 = (size_t)row * N + col;
                size_t i1 = (size_t)(row + 8) * N + col;
                *reinterpret_cast<uint32_t*>(&Chi[i0]) = pack_f16(v00, v01);
                *reinterpret_cast<uint32_t*>(&Chi[i1]) = pack_f16(v10, v11);
            } else {
                float2 w0 = {v00, v01}, w1 = {v10, v11};
                *reinterpret_cast<float2*>(&Cf[(size_t)row * N + col])       = w0;
                *reinterpret_cast<float2*>(&Cf[(size_t)(row + 8) * N + col]) = w1;
            }
        }
    }
}

// ---------------------------------------------------------------------------
// Tensor-core flash attention, pure fp16, 128 threads (4 warps x 32 Q rows).
// Q pre-scaled by 1/sqrt(dh) in GEMM1 epilogue (no scale multiply here).
// V fragments shared across both row bands. KTILE=64 double-buffered,
// single barrier per iter, 2 CTAs/SM, heavy-first tile order.
// ---------------------------------------------------------------------------
#define LDQ 136
#define QTILE 128
#define KTILE 64
#define A_SM_KV (QTILE * LDQ)
#define A_KV_TILE (KTILE * LDQ)               // 8704 elems
#define A_KV_STAGE (2 * A_KV_TILE)            // K | V
#define ATTN_SMEM_ELEMS (A_SM_KV + 2 * A_KV_STAGE)
#define ATTN_SMEM_BYTES (ATTN_SMEM_ELEMS * 2) // 104448

__global__ __launch_bounds__(128, 2) void attn_tc_kernel(
    const fp16* __restrict__ qkvhi, fp16* __restrict__ ahi)
{
    extern __shared__ fp16 asmem[];
    const uint32_t sb = smem_u32(asmem);

    const int qt = (int)gridDim.x - 1 - (int)blockIdx.x;   // heavy tiles first
    const int h  = blockIdx.y;
    const int b  = blockIdx.z;

    const int tid  = threadIdx.x;
    const int lane = tid & 31;
    const int warp = tid >> 5;          // 0..3
    const int g    = lane >> 2;
    const int tig  = lane & 3;
    const int wr   = warp * 32;         // warp's 32-row band

    const int a_r  = lane & 15;
    const int a_c  = (lane >> 4) * 8;
    const int kb_r = ((lane >> 4) * 8) + (lane & 7);
    const int kb_c = ((lane >> 3) & 1) * 8;
    const int vb_r = (lane & 7) + ((lane >> 3) & 1) * 8;
    const int vb_c = (lane >> 4) * 8;

    const size_t qoff = (size_t)(b * SEQ) * QKV_N + h * DH;
    const size_t koff = qoff + DM;
    const size_t voff = qoff + 2 * DM;

    const int njt = 2 * qt + 2;

    auto issue_kv = [&](int j) {
        if (j < njt) {
            uint32_t stb = sb + (uint32_t)(A_SM_KV + (j & 1) * A_KV_STAGE) * 2;
#pragma unroll
            for (int jj = 0; jj < 16; jj++) {
                const int tile = jj >> 3;
                int q  = tid + (jj & 7) * 128;
                int r  = q >> 4;
                int ch = (q & 15) << 3;
                size_t grow = (size_t)(j * KTILE + r) * QKV_N + ch;
                const fp16* src = qkvhi + (tile == 0 ? koff : voff) + grow;
                cp16(stb + (uint32_t)(tile * A_KV_TILE + r * LDQ + ch) * 2, src);
            }
        }
        CP_COMMIT();
    };

    {
#pragma unroll
        for (int jj = 0; jj < 16; jj++) {
            int q  = tid + jj * 128;
            int r  = q >> 4;
            int ch = (q & 15) << 3;
            const fp16* src = qkvhi + qoff
                              + (size_t)(qt * QTILE + r) * QKV_N + ch;
            cp16(sb + (uint32_t)(r * LDQ + ch) * 2, src);
        }
        issue_kv(0);   // Q + KV(0) in one group
    }

    float m[2][2], l[2][2];
#pragma unroll
    for (int mt = 0; mt < 2; mt++) {
        m[mt][0] = -INFINITY; m[mt][1] = -INFINITY;
        l[mt][0] = 0.0f;      l[mt][1] = 0.0f;
    }
    float o[2][16][4];
#pragma unroll
    for (int mt = 0; mt < 2; mt++)
#pragma unroll
        for (int nt = 0; nt < 16; nt++)
#pragma unroll
            for (int i = 0; i < 4; i++) o[mt][nt][i] = 0.0f;

    const int rowbase = qt * QTILE + wr;

    for (int j = 0; j < njt; j++) {
        CP_WAIT(0);
        __syncthreads();
        issue_kv(j + 1);

        if (j * KTILE <= rowbase + 31) {
            const uint32_t kvb = sb + (uint32_t)(A_SM_KV + (j & 1) * A_KV_STAGE) * 2;
            const uint32_t khi_b = kvb + (uint32_t)(kb_r * LDQ + kb_c) * 2;
            const uint32_t vhi_b = kvb + (uint32_t)(A_KV_TILE + vb_r * LDQ + vb_c) * 2;

            // ---- S = Q @ K^T (both 16-row bands; Q pre-scaled) ----
            float s[2][8][4];
#pragma unroll
            for (int mt = 0; mt < 2; mt++)
#pragma unroll
                for (int nt = 0; nt < 8; nt++)
#pragma unroll
                    for (int i = 0; i < 4; i++) s[mt][nt][i] = 0.0f;

#pragma unroll
            for (int ks = 0; ks < 8; ks++) {
                uint32_t ah[2][4];
#pragma unroll
                for (int mt = 0; mt < 2; mt++) {
                    uint32_t ao = sb + (uint32_t)((wr + mt * 16 + a_r) * LDQ
                                                  + ks * 16 + a_c) * 2;
                    ldmatrix_x4(ah[mt][0], ah[mt][1], ah[mt][2], ah[mt][3], ao);
                }
#pragma unroll
                for (int ntp = 0; ntp < 4; ntp++) {
                    uint32_t bh[4];
                    ldmatrix_x4(bh[0], bh[1], bh[2], bh[3],
                                khi_b + (uint32_t)(ntp * 16 * LDQ + ks * 16) * 2);
#pragma unroll
                    for (int mt = 0; mt < 2; mt++) {
                        mma_f16(s[mt][2 * ntp],     ah[mt], bh);
                        mma_f16(s[mt][2 * ntp + 1], ah[mt], bh + 2);
                    }
                }
            }

            const int jc = j * KTILE;
#pragma unroll
            for (int mt = 0; mt < 2; mt++) {
                const int rowg  = rowbase + mt * 16 + g;
                const int rowg8 = rowg + 8;

                if (jc + KTILE - 1 > rowg) {
#pragma unroll
                    for (int nt = 0; nt < 8; nt++) {
                        int c0 = jc + nt * 8 + tig * 2;
                        if (c0     > rowg) s[mt][nt][0] = -1e30f;
                        if (c0 + 1 > rowg) s[mt][nt][1] = -1e30f;
                    }
                }
                if (jc + KTILE - 1 > rowg8) {
#pragma unroll
                    for (int nt = 0; nt < 8; nt++) {
                        int c0 = jc + nt * 8 + tig * 2;
                        if (c0     > rowg8) s[mt][nt][2] = -1e30f;
                        if (c0 + 1 > rowg8) s[mt][nt][3] = -1e30f;
                    }
                }

                float mt0 = -1e30f, mt1 = -1e30f;
#pragma unroll
                for (int nt = 0; nt < 8; nt++) {
                    mt0 = fmaxf(mt0, fmaxf(s[mt][nt][0], s[mt][nt][1]));
                    mt1 = fmaxf(mt1, fmaxf(s[mt][nt][2], s[mt][nt][3]));
                }
                mt0 = fmaxf(mt0, __shfl_xor_sync(0xffffffffu, mt0, 1));
                mt0 = fmaxf(mt0, __shfl_xor_sync(0xffffffffu, mt0, 2));
                mt1 = fmaxf(mt1, __shfl_xor_sync(0xffffffffu, mt1, 1));
                mt1 = fmaxf(mt1, __shfl_xor_sync(0xffffffffu, mt1, 2));

                float mn0 = fmaxf(m[mt][0], mt0);
                float mn1 = fmaxf(m[mt][1], mt1);
                float al0 = __expf(m[mt][0] - mn0);
                float al1 = __expf(m[mt][1] - mn1);
                m[mt][0] = mn0; m[mt][1] = mn1;

                float rs0 = 0.0f, rs1 = 0.0f;
#pragma unroll
                for (int nt = 0; nt < 8; nt++) {
                    s[mt][nt][0] = __expf(s[mt][nt][0] - mn0); rs0 += s[mt][nt][0];
                    s[mt][nt][1] = __expf(s[mt][nt][1] - mn0); rs0 += s[mt][nt][1];
                    s[mt][nt][2] = __expf(s[mt][nt][2] - mn1); rs1 += s[mt][nt][2];
                    s[mt][nt][3] = __expf(s[mt][nt][3] - mn1); rs1 += s[mt][nt][3];
                }
                rs0 += __shfl_xor_sync(0xffffffffu, rs0, 1);
                rs0 += __shfl_xor_sync(0xffffffffu, rs0, 2);
                rs1 += __shfl_xor_sync(0xffffffffu, rs1, 1);
                rs1 += __shfl_xor_sync(0xffffffffu, rs1, 2);

                l[mt][0] = l[mt][0] * al0 + rs0;
                l[mt][1] = l[mt][1] * al1 + rs1;
#pragma unroll
                for (int nt = 0; nt < 16; nt++) {
                    o[mt][nt][0] *= al0; o[mt][nt][1] *= al0;
                    o[mt][nt][2] *= al1; o[mt][nt][3] *= al1;
                }
            }

            // ---- O += P @ V (V fragments shared across both bands) ----
#pragma unroll
            for (int ks = 0; ks < 4; ks++) {
                uint32_t ph[2][4];
#pragma unroll
                for (int mt = 0; mt < 2; mt++)
#pragma unroll
                    for (int half = 0; half < 2; half++) {
                        ph[mt][0 + 2 * half] = pack_f16(s[mt][2 * ks + half][0],
                                                        s[mt][2 * ks + half][1]);
                        ph[mt][1 + 2 * half] = pack_f16(s[mt][2 * ks + half][2],
                                                        s[mt][2 * ks + half][3]);
                    }
#pragma unroll
                for (int ntp = 0; ntp < 8; ntp++) {
                    uint32_t bh[4];
                    ldmatrix_x4_trans(bh[0], bh[1], bh[2], bh[3],
                                      vhi_b + (uint32_t)(ks * 16 * LDQ + ntp * 16) * 2);
#pragma unroll
                    for (int mt = 0; mt < 2; mt++) {
                        mma_f16(o[mt][2 * ntp],     ph[mt], bh);
                        mma_f16(o[mt][2 * ntp + 1], ph[mt], bh + 2);
                    }
                }
            }
        }
    }

    // ---- normalize + fp16 store (feeds GEMM2) ----
#pragma unroll
    for (int mt = 0; mt < 2; mt++) {
        const float inv0 = 1.0f / l[mt][0];
        const float inv1 = 1.0f / l[mt][1];
        const int rowg = rowbase + mt * 16 + g;
#pragma unroll
        for (int nt = 0; nt < 16; nt++) {
            int col = h * DH + nt * 8 + tig * 2;
            size_t i0 = (size_t)(b * SEQ + rowg)     * DM + col;
            size_t i1 = (size_t)(b * SEQ + rowg + 8) * DM + col;
            *reinterpret_cast<uint32_t*>(&ahi[i0]) =
                pack_f16(o[mt][nt][0] * inv0, o[mt][nt][1] * inv0);
            *reinterpret_cast<uint32_t*>(&ahi[i1]) =
                pack_f16(o[mt][nt][2] * inv1, o[mt][nt][3] * inv1);
        }
    }
}

// ---------------------------------------------------------------------------
extern "C" void kernel_launch(void* const* d_in, const int* in_sizes, int n_in,
                              void* d_out, int out_size)
{
    const float* x     = (const float*)d_in[0];
    const float* w_qkv = (const float*)d_in[1];
    const float* b_qkv = (const float*)d_in[2];
    const float* w_out = (const float*)d_in[3];
    const float* b_out = (const float*)d_in[4];
    float* out = (float*)d_out;

    fp16 *xh, *qh, *ahi, *wq, *wo;
    cudaGetSymbolAddress((void**)&xh,  g_xh);
    cudaGetSymbolAddress((void**)&qh,  g_qkvhi);
    cudaGetSymbolAddress((void**)&ahi, g_ahi);
    cudaGetSymbolAddress((void**)&wq,  g_wqt);
    cudaGetSymbolAddress((void**)&wo,  g_wot);

    cudaFuncSetAttribute(attn_tc_kernel,
                         cudaFuncAttributeMaxDynamicSharedMemorySize,
                         ATTN_SMEM_BYTES);
    cudaFuncSetAttribute(gemm_tc_kernel<true>,
                         cudaFuncAttributeMaxDynamicSharedMemorySize,
                         GEMM_SMEM_BYTES);
    cudaFuncSetAttribute(gemm_tc_kernel<false>,
                         cudaFuncAttributeMaxDynamicSharedMemorySize,
                         GEMM_SMEM_BYTES);

    const float scale = 0.08838834764831845f;   // 1/sqrt(128)

    // 0a) convert x -> fp16
    {
        int n4 = (MROWS * DM) / 4;
        cvt_f16_kernel<<<n4 / 256, 256>>>((const float4*)x, (__half2*)xh, n4);
    }
    // 0b) transpose weights -> fp16
    {
        dim3 b32(32, 8);
        dim3 gq(QKV_N / 32, DM / 32);
        transpose_f16_kernel<<<gq, b32>>>(w_qkv, wq, DM, QKV_N);
        dim3 go(DM / 32, DM / 32);
        transpose_f16_kernel<<<go, b32>>>(w_out, wo, DM, DM);
    }
    // 1) QKV projection (static grid; Q cols pre-scaled by 1/sqrt(dh)) -> fp16
    {
        dim3 g1(QKV_N / 128, MROWS / 128);
        gemm_tc_kernel<true><<<g1, 128, GEMM_SMEM_BYTES>>>(
            xh, wq, b_qkv, nullptr, qh, MROWS, QKV_N, DM, scale, DM);
    }
    // 2) Attention (pure fp16, wide warp tiles, 2 CTAs/SM) -> fp16 output
    {
        dim3 g2(SEQ / QTILE, NH, BATCH);
        attn_tc_kernel<<<g2, 128, ATTN_SMEM_BYTES>>>(qh, ahi);
    }
    // 3) Output projection (static grid) -> fp32
    {
        dim3 g3(DM / 128, MROWS / 128);
        gemm_tc_kernel<false><<<g3, 128, GEMM_SMEM_BYTES>>>(
            ahi, wo, b_out, out, nullptr, MROWS, DM, DM, 1.0f, 0);
    }
}